// round 1
// baseline (speedup 1.0000x reference)
#include <cuda_runtime.h>

// YoloV1Loss: pred/label (16384, 30, 7, 7) fp32 -> scalar fp32.
// Memory-bound streaming reduction. One thread per spatial cell (b, s).

#define BLOCK 256
static constexpr int BATCH  = 16384;
static constexpr int NCH    = 30;
static constexpr int NROW   = 7;
static constexpr int NCOL   = 7;
static constexpr int SPAT   = NROW * NCOL;          // 49
static constexpr int CHSTR  = SPAT;                 // channel stride in floats
static constexpr int BSTR   = NCH * SPAT;           // 1470
static constexpr int NCELLS = BATCH * SPAT;         // 802816
static constexpr int NBLOCKS = (NCELLS + BLOCK - 1) / BLOCK;  // 3136

__device__ float g_partials[NBLOCKS];

__device__ __forceinline__ float iou_calc(float ax1, float ay1, float ax2, float ay2,
                                          float bx1, float by1, float bx2, float by2) {
    float iw = fmaxf(fminf(ax2, bx2) - fmaxf(ax1, bx1), 0.0f);
    float ih = fmaxf(fminf(ay2, by2) - fmaxf(ay1, by1), 0.0f);
    float inter = iw * ih;
    float area_a = (ax2 - ax1) * (ay2 - ay1);
    float area_b = (bx2 - bx1) * (by2 - by1);
    return inter / (area_a + area_b - inter + 1e-10f);
}

__global__ void __launch_bounds__(BLOCK) yolo_loss_kernel(
    const float* __restrict__ pred, const float* __restrict__ label) {
    int t = blockIdx.x * BLOCK + threadIdx.x;

    float cell = 0.0f;
    if (t < NCELLS) {
        int b = t / SPAT;
        int s = t - b * SPAT;
        int row = s / NCOL;
        int col = s - row * NCOL;

        const float* pp = pred  + (size_t)b * BSTR + s;
        const float* ll = label + (size_t)b * BSTR + s;

        float p[NCH], lb[NCH];
        #pragma unroll
        for (int c = 0; c < NCH; c++) {
            p[c]  = __ldg(pp + c * CHSTR);
            lb[c] = __ldg(ll + c * CHSTR);
        }

        const float inv = 1.0f / (float)NCOL;   // nrow == ncol == 7
        float fc = (float)col, fr = (float)row;

        // pred box 1 (channels 0..3)
        float cx = (p[0] + fc) * inv, cy = (p[1] + fr) * inv;
        float a1x1 = cx - 0.5f * p[2], a1y1 = cy - 0.5f * p[3];
        float a1x2 = cx + 0.5f * p[2], a1y2 = cy + 0.5f * p[3];
        // pred box 2 (channels 5..8)
        cx = (p[5] + fc) * inv; cy = (p[6] + fr) * inv;
        float a2x1 = cx - 0.5f * p[7], a2y1 = cy - 0.5f * p[8];
        float a2x2 = cx + 0.5f * p[7], a2y2 = cy + 0.5f * p[8];
        // label box (channels 0..3)
        cx = (lb[0] + fc) * inv; cy = (lb[1] + fr) * inv;
        float lx1 = cx - 0.5f * lb[2], ly1 = cy - 0.5f * lb[3];
        float lx2 = cx + 0.5f * lb[2], ly2 = cy + 0.5f * lb[3];

        float iou1 = iou_calc(a1x1, a1y1, a1x2, a1y2, lx1, ly1, lx2, ly2);
        float iou2 = iou_calc(a2x1, a2y1, a2x2, a2y2, lx1, ly1, lx2, ly2);
        bool choose1 = (iou1 >= iou2);

        float d0 = p[0] - lb[0], d1 = p[1] - lb[1];
        float sw1 = sqrtf(p[2]) - sqrtf(lb[2]);
        float sh1 = sqrtf(p[3]) - sqrtf(lb[3]);
        float coord1 = 5.0f * (d0 * d0 + d1 * d1) + sw1 * sw1 + sh1 * sh1;

        float e0 = p[5] - lb[5], e1 = p[6] - lb[6];
        float sw2 = sqrtf(p[7]) - sqrtf(lb[7]);
        float sh2 = sqrtf(p[8]) - sqrtf(lb[8]);
        float coord2 = 5.0f * (e0 * e0 + e1 * e1) + sw2 * sw2 + sh2 * sh2;

        float o1 = p[4] - iou1; float obj1 = o1 * o1;
        float o2 = p[9] - iou2; float obj2 = o2 * o2;

        float coord      = choose1 ? coord1 : coord2;
        float obj_conf   = choose1 ? obj1   : obj2;
        float noobj_conf = 0.5f * (choose1 ? obj2 : obj1);

        float class_l = 0.0f;
        #pragma unroll
        for (int c = 10; c < NCH; c++) {
            float d = p[c] - lb[c];
            class_l += d * d;
        }

        float obj_cell = coord + obj_conf + noobj_conf + class_l;
        float nsum = p[4] + p[9];
        float noobj_cell = 0.5f * nsum * nsum;

        cell = (lb[4] == 1.0f) ? obj_cell : noobj_cell;
    }

    // Deterministic block reduction: warp shuffle -> smem -> warp shuffle.
    #pragma unroll
    for (int off = 16; off > 0; off >>= 1)
        cell += __shfl_down_sync(0xFFFFFFFFu, cell, off);

    __shared__ float warp_sums[BLOCK / 32];
    if ((threadIdx.x & 31) == 0) warp_sums[threadIdx.x >> 5] = cell;
    __syncthreads();

    if (threadIdx.x < 32) {
        float v = (threadIdx.x < BLOCK / 32) ? warp_sums[threadIdx.x] : 0.0f;
        #pragma unroll
        for (int off = 16; off > 0; off >>= 1)
            v += __shfl_down_sync(0xFFFFFFFFu, v, off);
        if (threadIdx.x == 0) g_partials[blockIdx.x] = v;
    }
}

__global__ void __launch_bounds__(1024) yolo_reduce_kernel(float* __restrict__ out) {
    __shared__ float sm[1024];
    float s = 0.0f;
    for (int i = threadIdx.x; i < NBLOCKS; i += 1024)
        s += g_partials[i];
    sm[threadIdx.x] = s;
    __syncthreads();
    #pragma unroll
    for (int k = 512; k > 0; k >>= 1) {
        if (threadIdx.x < k) sm[threadIdx.x] += sm[threadIdx.x + k];
        __syncthreads();
    }
    if (threadIdx.x == 0) out[0] = sm[0] * (1.0f / (float)BATCH);
}

extern "C" void kernel_launch(void* const* d_in, const int* in_sizes, int n_in,
                              void* d_out, int out_size) {
    const float* pred  = (const float*)d_in[0];
    const float* label = (const float*)d_in[1];
    float* out = (float*)d_out;

    yolo_loss_kernel<<<NBLOCKS, BLOCK>>>(pred, label);
    yolo_reduce_kernel<<<1, 1024>>>(out);
}

// round 3
// speedup vs baseline: 1.1743x; 1.1743x over previous
#include <cuda_runtime.h>

// YoloV1Loss: pred/label (16384, 30, 7, 7) fp32 -> scalar fp32.
// Single fused kernel: streaming per-cell loss + deterministic two-level
// reduction, final block pattern (threadfence + ticket, counter self-resets).

#define BLOCK 256
#define CPT   4                                    // cells per thread
static constexpr int BATCH  = 16384;
static constexpr int NCH    = 30;
static constexpr int NCOL   = 7;
static constexpr int SPAT   = 49;
static constexpr int CHSTR  = SPAT;
static constexpr int BSTR   = NCH * SPAT;          // 1470
static constexpr int NCELLS = BATCH * SPAT;        // 802816
static constexpr int GRID   = NCELLS / (BLOCK * CPT); // 784 exactly

__device__ float        g_partials[GRID];
__device__ unsigned int g_count = 0;

__device__ __forceinline__ float iou_calc(float ax1, float ay1, float ax2, float ay2,
                                          float bx1, float by1, float bx2, float by2) {
    float iw = fmaxf(fminf(ax2, bx2) - fmaxf(ax1, bx1), 0.0f);
    float ih = fmaxf(fminf(ay2, by2) - fmaxf(ay1, by1), 0.0f);
    float inter = iw * ih;
    float area_a = (ax2 - ax1) * (ay2 - ay1);
    float area_b = (bx2 - bx1) * (by2 - by1);
    return inter / (area_a + area_b - inter + 1e-10f);
}

__device__ __forceinline__ float cell_loss(const float* __restrict__ pred,
                                           const float* __restrict__ label,
                                           int t) {
    int b = t / SPAT;
    int s = t - b * SPAT;
    int row = s / NCOL;
    int col = s - row * NCOL;

    const float* pp = pred  + (size_t)b * BSTR + s;
    const float* ll = label + (size_t)b * BSTR + s;

    float p[NCH], lb[NCH];
    #pragma unroll
    for (int c = 0; c < NCH; c++) {
        p[c]  = __ldg(pp + c * CHSTR);
        lb[c] = __ldg(ll + c * CHSTR);
    }

    const float inv = 1.0f / (float)NCOL;
    float fc = (float)col, fr = (float)row;

    float cx = (p[0] + fc) * inv, cy = (p[1] + fr) * inv;
    float a1x1 = cx - 0.5f * p[2], a1y1 = cy - 0.5f * p[3];
    float a1x2 = cx + 0.5f * p[2], a1y2 = cy + 0.5f * p[3];
    cx = (p[5] + fc) * inv; cy = (p[6] + fr) * inv;
    float a2x1 = cx - 0.5f * p[7], a2y1 = cy - 0.5f * p[8];
    float a2x2 = cx + 0.5f * p[7], a2y2 = cy + 0.5f * p[8];
    cx = (lb[0] + fc) * inv; cy = (lb[1] + fr) * inv;
    float lx1 = cx - 0.5f * lb[2], ly1 = cy - 0.5f * lb[3];
    float lx2 = cx + 0.5f * lb[2], ly2 = cy + 0.5f * lb[3];

    float iou1 = iou_calc(a1x1, a1y1, a1x2, a1y2, lx1, ly1, lx2, ly2);
    float iou2 = iou_calc(a2x1, a2y1, a2x2, a2y2, lx1, ly1, lx2, ly2);
    bool choose1 = (iou1 >= iou2);

    float d0 = p[0] - lb[0], d1 = p[1] - lb[1];
    float sw1 = sqrtf(p[2]) - sqrtf(lb[2]);
    float sh1 = sqrtf(p[3]) - sqrtf(lb[3]);
    float coord1 = 5.0f * (d0 * d0 + d1 * d1) + sw1 * sw1 + sh1 * sh1;

    float e0 = p[5] - lb[5], e1 = p[6] - lb[6];
    float sw2 = sqrtf(p[7]) - sqrtf(lb[7]);
    float sh2 = sqrtf(p[8]) - sqrtf(lb[8]);
    float coord2 = 5.0f * (e0 * e0 + e1 * e1) + sw2 * sw2 + sh2 * sh2;

    float o1 = p[4] - iou1; float obj1 = o1 * o1;
    float o2 = p[9] - iou2; float obj2 = o2 * o2;

    float coord      = choose1 ? coord1 : coord2;
    float obj_conf   = choose1 ? obj1   : obj2;
    float noobj_conf = 0.5f * (choose1 ? obj2 : obj1);

    float class_l = 0.0f;
    #pragma unroll
    for (int c = 10; c < NCH; c++) {
        float d = p[c] - lb[c];
        class_l += d * d;
    }

    float obj_cell = coord + obj_conf + noobj_conf + class_l;
    float nsum = p[4] + p[9];
    float noobj_cell = 0.5f * nsum * nsum;

    return (lb[4] == 1.0f) ? obj_cell : noobj_cell;
}

__global__ void __launch_bounds__(BLOCK) yolo_loss_fused(
    const float* __restrict__ pred, const float* __restrict__ label,
    float* __restrict__ out) {
    float acc = 0.0f;
    // Coalesced grid-stride: consecutive threads -> consecutive cells each iter.
    #pragma unroll
    for (int i = 0; i < CPT; i++) {
        int t = (i * GRID + blockIdx.x) * BLOCK + threadIdx.x;
        acc += cell_loss(pred, label, t);
    }

    // Block reduction (deterministic): warp shuffle -> smem -> warp shuffle.
    #pragma unroll
    for (int off = 16; off > 0; off >>= 1)
        acc += __shfl_down_sync(0xFFFFFFFFu, acc, off);

    __shared__ float warp_sums[BLOCK / 32];
    if ((threadIdx.x & 31) == 0) warp_sums[threadIdx.x >> 5] = acc;
    __syncthreads();

    __shared__ bool is_last;
    if (threadIdx.x < 32) {
        float v = (threadIdx.x < BLOCK / 32) ? warp_sums[threadIdx.x] : 0.0f;
        #pragma unroll
        for (int off = 16; off > 0; off >>= 1)
            v += __shfl_down_sync(0xFFFFFFFFu, v, off);
        if (threadIdx.x == 0) {
            g_partials[blockIdx.x] = v;
            __threadfence();
            unsigned int ticket = atomicAdd(&g_count, 1u);
            is_last = (ticket == GRID - 1);
        }
    }
    __syncthreads();

    // Final block: deterministic fixed-order sum of all partials.
    if (is_last) {
        float s = 0.0f;
        for (int i = threadIdx.x; i < GRID; i += BLOCK)
            s += g_partials[i];
        #pragma unroll
        for (int off = 16; off > 0; off >>= 1)
            s += __shfl_down_sync(0xFFFFFFFFu, s, off);

        __shared__ float fw[BLOCK / 32];
        if ((threadIdx.x & 31) == 0) fw[threadIdx.x >> 5] = s;
        __syncthreads();
        if (threadIdx.x < 32) {
            float v = (threadIdx.x < BLOCK / 32) ? fw[threadIdx.x] : 0.0f;
            #pragma unroll
            for (int off = 16; off > 0; off >>= 1)
                v += __shfl_down_sync(0xFFFFFFFFu, v, off);
            if (threadIdx.x == 0) {
                out[0] = v * (1.0f / (float)BATCH);
                g_count = 0;   // reset for next graph replay
            }
        }
    }
}

extern "C" void kernel_launch(void* const* d_in, const int* in_sizes, int n_in,
                              void* d_out, int out_size) {
    const float* pred  = (const float*)d_in[0];
    const float* label = (const float*)d_in[1];
    float* out = (float*)d_out;
    yolo_loss_fused<<<GRID, BLOCK>>>(pred, label, out);
}

// round 4
// speedup vs baseline: 1.2748x; 1.0856x over previous
#include <cuda_runtime.h>

// YoloV1Loss: pred/label (16384, 30, 7, 7) fp32 -> scalar fp32.
// Fused streaming reduction. Register-lean: class channels (10..29) are
// stream-accumulated so only channels 0..9 are live -> <=64 regs, 4 blocks/SM.

#define BLOCK 256
#define CPT   2                                    // cells per thread
static constexpr int BATCH  = 16384;
static constexpr int NCH    = 30;
static constexpr int NCOL   = 7;
static constexpr int SPAT   = 49;
static constexpr int CHSTR  = SPAT;
static constexpr int BSTR   = NCH * SPAT;          // 1470
static constexpr int NCELLS = BATCH * SPAT;        // 802816
static constexpr int GRID   = NCELLS / (BLOCK * CPT); // 1568 exactly

__device__ float        g_partials[GRID];
__device__ unsigned int g_count = 0;

__device__ __forceinline__ float iou_calc(float ax1, float ay1, float ax2, float ay2,
                                          float bx1, float by1, float bx2, float by2) {
    float iw = fmaxf(fminf(ax2, bx2) - fmaxf(ax1, bx1), 0.0f);
    float ih = fmaxf(fminf(ay2, by2) - fmaxf(ay1, by1), 0.0f);
    float inter = iw * ih;
    float area_a = (ax2 - ax1) * (ay2 - ay1);
    float area_b = (bx2 - bx1) * (by2 - by1);
    return inter / (area_a + area_b - inter + 1e-10f);
}

__device__ __forceinline__ float cell_loss(const float* __restrict__ pred,
                                           const float* __restrict__ label,
                                           int t) {
    int b = t / SPAT;
    int s = t - b * SPAT;
    int row = s / NCOL;
    int col = s - row * NCOL;

    const float* pp = pred  + (size_t)b * BSTR + s;
    const float* ll = label + (size_t)b * BSTR + s;

    // Live header channels only: pred 0..9, label 0..8 (+label4).
    float p[10], lb[9];
    #pragma unroll
    for (int c = 0; c < 10; c++) p[c]  = __ldg(pp + c * CHSTR);
    #pragma unroll
    for (int c = 0; c < 9;  c++) lb[c] = __ldg(ll + c * CHSTR);

    // Stream-accumulate class loss (channels 10..29); nothing stays live.
    float class_l = 0.0f;
    #pragma unroll
    for (int c = 10; c < NCH; c++) {
        float pv = __ldg(pp + c * CHSTR);
        float lv = __ldg(ll + c * CHSTR);
        float d = pv - lv;
        class_l = fmaf(d, d, class_l);
    }

    const float inv = 1.0f / (float)NCOL;
    float fc = (float)col, fr = (float)row;

    float cx = (p[0] + fc) * inv, cy = (p[1] + fr) * inv;
    float a1x1 = cx - 0.5f * p[2], a1y1 = cy - 0.5f * p[3];
    float a1x2 = cx + 0.5f * p[2], a1y2 = cy + 0.5f * p[3];
    cx = (p[5] + fc) * inv; cy = (p[6] + fr) * inv;
    float a2x1 = cx - 0.5f * p[7], a2y1 = cy - 0.5f * p[8];
    float a2x2 = cx + 0.5f * p[7], a2y2 = cy + 0.5f * p[8];
    cx = (lb[0] + fc) * inv; cy = (lb[1] + fr) * inv;
    float lx1 = cx - 0.5f * lb[2], ly1 = cy - 0.5f * lb[3];
    float lx2 = cx + 0.5f * lb[2], ly2 = cy + 0.5f * lb[3];

    float iou1 = iou_calc(a1x1, a1y1, a1x2, a1y2, lx1, ly1, lx2, ly2);
    float iou2 = iou_calc(a2x1, a2y1, a2x2, a2y2, lx1, ly1, lx2, ly2);
    bool choose1 = (iou1 >= iou2);

    float d0 = p[0] - lb[0], d1 = p[1] - lb[1];
    float sw1 = sqrtf(p[2]) - sqrtf(lb[2]);
    float sh1 = sqrtf(p[3]) - sqrtf(lb[3]);
    float coord1 = 5.0f * (d0 * d0 + d1 * d1) + sw1 * sw1 + sh1 * sh1;

    float e0 = p[5] - lb[5], e1 = p[6] - lb[6];
    float sw2 = sqrtf(p[7]) - sqrtf(lb[7]);
    float sh2 = sqrtf(p[8]) - sqrtf(lb[8]);
    float coord2 = 5.0f * (e0 * e0 + e1 * e1) + sw2 * sw2 + sh2 * sh2;

    float o1 = p[4] - iou1; float obj1 = o1 * o1;
    float o2 = p[9] - iou2; float obj2 = o2 * o2;

    float coord      = choose1 ? coord1 : coord2;
    float obj_conf   = choose1 ? obj1   : obj2;
    float noobj_conf = 0.5f * (choose1 ? obj2 : obj1);

    float obj_cell = coord + obj_conf + noobj_conf + class_l;
    float nsum = p[4] + p[9];
    float noobj_cell = 0.5f * nsum * nsum;

    return (lb[4] == 1.0f) ? obj_cell : noobj_cell;
}

__global__ void __launch_bounds__(BLOCK, 4) yolo_loss_fused(
    const float* __restrict__ pred, const float* __restrict__ label,
    float* __restrict__ out) {
    float acc = 0.0f;
    #pragma unroll
    for (int i = 0; i < CPT; i++) {
        int t = (i * GRID + blockIdx.x) * BLOCK + threadIdx.x;
        acc += cell_loss(pred, label, t);
    }

    // Deterministic block reduction.
    #pragma unroll
    for (int off = 16; off > 0; off >>= 1)
        acc += __shfl_down_sync(0xFFFFFFFFu, acc, off);

    __shared__ float warp_sums[BLOCK / 32];
    if ((threadIdx.x & 31) == 0) warp_sums[threadIdx.x >> 5] = acc;
    __syncthreads();

    __shared__ bool is_last;
    if (threadIdx.x < 32) {
        float v = (threadIdx.x < BLOCK / 32) ? warp_sums[threadIdx.x] : 0.0f;
        #pragma unroll
        for (int off = 16; off > 0; off >>= 1)
            v += __shfl_down_sync(0xFFFFFFFFu, v, off);
        if (threadIdx.x == 0) {
            g_partials[blockIdx.x] = v;
            __threadfence();
            unsigned int ticket = atomicAdd(&g_count, 1u);
            is_last = (ticket == GRID - 1);
        }
    }
    __syncthreads();

    // Final block: deterministic fixed-order sum of all partials.
    if (is_last) {
        float s = 0.0f;
        for (int i = threadIdx.x; i < GRID; i += BLOCK)
            s += g_partials[i];
        #pragma unroll
        for (int off = 16; off > 0; off >>= 1)
            s += __shfl_down_sync(0xFFFFFFFFu, s, off);

        __shared__ float fw[BLOCK / 32];
        if ((threadIdx.x & 31) == 0) fw[threadIdx.x >> 5] = s;
        __syncthreads();
        if (threadIdx.x < 32) {
            float v = (threadIdx.x < BLOCK / 32) ? fw[threadIdx.x] : 0.0f;
            #pragma unroll
            for (int off = 16; off > 0; off >>= 1)
                v += __shfl_down_sync(0xFFFFFFFFu, v, off);
            if (threadIdx.x == 0) {
                out[0] = v * (1.0f / (float)BATCH);
                g_count = 0;   // reset for next graph replay
            }
        }
    }
}

extern "C" void kernel_launch(void* const* d_in, const int* in_sizes, int n_in,
                              void* d_out, int out_size) {
    const float* pred  = (const float*)d_in[0];
    const float* label = (const float*)d_in[1];
    float* out = (float*)d_out;
    yolo_loss_fused<<<GRID, BLOCK>>>(pred, label, out);
}